// round 13
// baseline (speedup 1.0000x reference)
#include <cuda_runtime.h>

// x: [N=256, 3, 3, num=256, F=128] fp32, contiguous.
// out: [N, 3, 3, G=128, F=128] fp32.
// Winner per pair = larger rotation angle acos(clip((tr-1)/2,-1,1));
// acos decreasing => winner = smaller clamp(tr,-1,3); ties -> candidate 0.
//
// R13: R9 body (best DRAM% = 84.1: __ldcs/__stcs, diag-first phasing,
// 38 regs) with CTA size stepped DOWN the measured trend:
//   512 thr -> 83.1% | 256 thr -> 84.1% | this: 128 thr, occ-12 (48 w/SM).
// Smaller CTAs give the scheduler finer interleave of independent warps'
// load batches. All other levers (persistent grid, write-back stores,
// v8 ld/st, larger CTAs) measured and reverted as regressions. Traffic is
// at the 453 MB floor; wall is within ~2.5% of the achieved-BW bound.

#define N_    256
#define G_    128
#define F4_   32                      // 128 floats = 32 float4
#define TOT   (N_ * G_ * F4_)         // 1,048,576 threads
#define BLK   128

// strides in float4 units
#define XSD   8192                    // per (d1*3+d2) step
#define XSM   32                      // per num step
#define XSN   73728                   // 9*8192
#define OSD   4096
#define OSG   32
#define OSN   36864                   // 9*4096

__device__ __forceinline__ float clamp_tr(float t) {
    return fminf(fmaxf(t, -1.0f), 3.0f);
}

__device__ __forceinline__ float4 sel4(bool sx, bool sy, bool sz, bool sw,
                                       const float4& a, const float4& b) {
    float4 r;
    r.x = sx ? b.x : a.x;
    r.y = sy ? b.y : a.y;
    r.z = sz ? b.z : a.z;
    r.w = sw ? b.w : a.w;
    return r;
}

__global__ __launch_bounds__(BLK, 12)
void Pooling_5866925326754_kernel(const float4* __restrict__ xv,
                                  float4* __restrict__ ov) {
    int idx = blockIdx.x * BLK + threadIdx.x;

    int f4 = idx & (F4_ - 1);
    int g  = (idx >> 5) & (G_ - 1);
    int n  = idx >> 12;

    const float4* pa = xv + n * XSN + (2 * g) * XSM + f4;
    const float4* pb = pa + XSM;
    float4*       po = ov + n * OSN + g * OSG + f4;

    // ---- phase 1: diagonals (6 loads) -> mask -> retire d=0,4,8 ----
    float4 a0 = __ldcs(pa + 0 * XSD);
    float4 a4 = __ldcs(pa + 4 * XSD);
    float4 a8 = __ldcs(pa + 8 * XSD);
    float4 b0 = __ldcs(pb + 0 * XSD);
    float4 b4 = __ldcs(pb + 4 * XSD);
    float4 b8 = __ldcs(pb + 8 * XSD);

    // candidate 1 wins only on strictly smaller clamped trace
    bool sx = clamp_tr(b0.x + b4.x + b8.x) < clamp_tr(a0.x + a4.x + a8.x);
    bool sy = clamp_tr(b0.y + b4.y + b8.y) < clamp_tr(a0.y + a4.y + a8.y);
    bool sz = clamp_tr(b0.z + b4.z + b8.z) < clamp_tr(a0.z + a4.z + a8.z);
    bool sw = clamp_tr(b0.w + b4.w + b8.w) < clamp_tr(a0.w + a4.w + a8.w);

    __stcs(po + 0 * OSD, sel4(sx, sy, sz, sw, a0, b0));
    __stcs(po + 4 * OSD, sel4(sx, sy, sz, sw, a4, b4));
    __stcs(po + 8 * OSD, sel4(sx, sy, sz, sw, a8, b8));

    // ---- phase 2a: off-diagonals d = 1,2,3 (6 loads, 3 stores) ----
    {
        float4 a1 = __ldcs(pa + 1 * XSD);
        float4 a2 = __ldcs(pa + 2 * XSD);
        float4 a3 = __ldcs(pa + 3 * XSD);
        float4 b1 = __ldcs(pb + 1 * XSD);
        float4 b2 = __ldcs(pb + 2 * XSD);
        float4 b3 = __ldcs(pb + 3 * XSD);
        __stcs(po + 1 * OSD, sel4(sx, sy, sz, sw, a1, b1));
        __stcs(po + 2 * OSD, sel4(sx, sy, sz, sw, a2, b2));
        __stcs(po + 3 * OSD, sel4(sx, sy, sz, sw, a3, b3));
    }

    // ---- phase 2b: off-diagonals d = 5,6,7 (6 loads, 3 stores) ----
    {
        float4 a5 = __ldcs(pa + 5 * XSD);
        float4 a6 = __ldcs(pa + 6 * XSD);
        float4 a7 = __ldcs(pa + 7 * XSD);
        float4 b5 = __ldcs(pb + 5 * XSD);
        float4 b6 = __ldcs(pb + 6 * XSD);
        float4 b7 = __ldcs(pb + 7 * XSD);
        __stcs(po + 5 * OSD, sel4(sx, sy, sz, sw, a5, b5));
        __stcs(po + 6 * OSD, sel4(sx, sy, sz, sw, a6, b6));
        __stcs(po + 7 * OSD, sel4(sx, sy, sz, sw, a7, b7));
    }
}

extern "C" void kernel_launch(void* const* d_in, const int* in_sizes, int n_in,
                              void* d_out, int out_size) {
    const float4* x = (const float4*)d_in[0];
    float4* out = (float4*)d_out;
    (void)in_sizes; (void)n_in; (void)out_size;
    Pooling_5866925326754_kernel<<<TOT / BLK, BLK>>>(x, out);
}

// round 14
// speedup vs baseline: 1.0023x; 1.0023x over previous
#include <cuda_runtime.h>

// x: [N=256, 3, 3, num=256, F=128] fp32, contiguous.
// out: [N, 3, 3, G=128, F=128] fp32.
// Winner per pair = larger rotation angle acos(clip((tr-1)/2,-1,1));
// acos decreasing => winner = smaller clamp(tr,-1,3); ties -> candidate 0.
//
// FINAL (locked R6 configuration — best measured wall time, 69.63us).
// Convergence evidence across 8 variants: traffic is at the 453 MB floor;
// kernel time pinned at 61.5-62.4us ncu across occupancy 32<->48 warps,
// batch depth 18<->6, persistent vs classic grid, 128/256/512-bit accesses,
// evict-first vs write-back stores. DRAM busy plateaus at 82-84%: the
// residual idle is mixed 2:1 read:write HBM3e turnaround across the 27
// interleaved address streams this layout requires — not SASS-addressable.
//
// Structure: one thread per (n,g,f4) float4 chunk. Diagonals first (6
// streaming loads) -> select mask from clamped traces -> retire d=0,4,8,
// then one deep 12-load batch for the off-diagonals. __ldcs/__stcs keep
// the zero-reuse streams out of L2's way.

#define N_    256
#define G_    128
#define F4_   32                      // 128 floats = 32 float4
#define TOT   (N_ * G_ * F4_)         // 1,048,576 threads

// strides in float4 units
#define XSD   8192                    // per (d1*3+d2) step
#define XSM   32                      // per num step
#define XSN   73728                   // 9*8192
#define OSD   4096
#define OSG   32
#define OSN   36864                   // 9*4096

__device__ __forceinline__ float clamp_tr(float t) {
    return fminf(fmaxf(t, -1.0f), 3.0f);
}

__device__ __forceinline__ float4 sel4(bool sx, bool sy, bool sz, bool sw,
                                       const float4& a, const float4& b) {
    float4 r;
    r.x = sx ? b.x : a.x;
    r.y = sy ? b.y : a.y;
    r.z = sz ? b.z : a.z;
    r.w = sw ? b.w : a.w;
    return r;
}

__global__ __launch_bounds__(256, 4)
void Pooling_5866925326754_kernel(const float4* __restrict__ xv,
                                  float4* __restrict__ ov) {
    int idx = blockIdx.x * blockDim.x + threadIdx.x;
    if (idx >= TOT) return;

    int f4 = idx & (F4_ - 1);
    int g  = (idx >> 5) & (G_ - 1);
    int n  = idx >> 12;

    const float4* pa = xv + n * XSN + (2 * g) * XSM + f4;
    const float4* pb = pa + XSM;
    float4*       po = ov + n * OSN + g * OSG + f4;

    // ---- diagonal loads (6), streaming policy ----
    float4 a0 = __ldcs(pa + 0 * XSD);
    float4 a4 = __ldcs(pa + 4 * XSD);
    float4 a8 = __ldcs(pa + 8 * XSD);
    float4 b0 = __ldcs(pb + 0 * XSD);
    float4 b4 = __ldcs(pb + 4 * XSD);
    float4 b8 = __ldcs(pb + 8 * XSD);

    // candidate 1 wins only on strictly smaller clamped trace
    bool sx = clamp_tr(b0.x + b4.x + b8.x) < clamp_tr(a0.x + a4.x + a8.x);
    bool sy = clamp_tr(b0.y + b4.y + b8.y) < clamp_tr(a0.y + a4.y + a8.y);
    bool sz = clamp_tr(b0.z + b4.z + b8.z) < clamp_tr(a0.z + a4.z + a8.z);
    bool sw = clamp_tr(b0.w + b4.w + b8.w) < clamp_tr(a0.w + a4.w + a8.w);

    // retire the diagonal positions immediately (frees 6 float4 of liveness)
    __stcs(po + 0 * OSD, sel4(sx, sy, sz, sw, a0, b0));
    __stcs(po + 4 * OSD, sel4(sx, sy, sz, sw, a4, b4));
    __stcs(po + 8 * OSD, sel4(sx, sy, sz, sw, a8, b8));

    // ---- off-diagonal positions: 1,2,3,5,6,7 (12-deep load batch) ----
    float4 a1 = __ldcs(pa + 1 * XSD);
    float4 a2 = __ldcs(pa + 2 * XSD);
    float4 a3 = __ldcs(pa + 3 * XSD);
    float4 a5 = __ldcs(pa + 5 * XSD);
    float4 a6 = __ldcs(pa + 6 * XSD);
    float4 a7 = __ldcs(pa + 7 * XSD);
    float4 b1 = __ldcs(pb + 1 * XSD);
    float4 b2 = __ldcs(pb + 2 * XSD);
    float4 b3 = __ldcs(pb + 3 * XSD);
    float4 b5 = __ldcs(pb + 5 * XSD);
    float4 b6 = __ldcs(pb + 6 * XSD);
    float4 b7 = __ldcs(pb + 7 * XSD);

    __stcs(po + 1 * OSD, sel4(sx, sy, sz, sw, a1, b1));
    __stcs(po + 2 * OSD, sel4(sx, sy, sz, sw, a2, b2));
    __stcs(po + 3 * OSD, sel4(sx, sy, sz, sw, a3, b3));
    __stcs(po + 5 * OSD, sel4(sx, sy, sz, sw, a5, b5));
    __stcs(po + 6 * OSD, sel4(sx, sy, sz, sw, a6, b6));
    __stcs(po + 7 * OSD, sel4(sx, sy, sz, sw, a7, b7));
}

extern "C" void kernel_launch(void* const* d_in, const int* in_sizes, int n_in,
                              void* d_out, int out_size) {
    const float4* x = (const float4*)d_in[0];
    float4* out = (float4*)d_out;
    (void)in_sizes; (void)n_in; (void)out_size;
    Pooling_5866925326754_kernel<<<TOT / 256, 256>>>(x, out);
}